// round 8
// baseline (speedup 1.0000x reference)
#include <cuda_runtime.h>
#include <stdint.h>

#define CC   128
#define CI   32
#define HH   128
#define WW   256
#define BB   8
#define HW   (HH*WW)

// Precomputed parameters (filled by prep kernel each launch; deterministic).
__device__ uint32_t g_w1m[CI][4];
__device__ float    g_inv1[CI], g_bb1[CI];
__device__ uint32_t g_w2m[CI][9];
__device__ float    g_inv2[CI], g_bb2[CI];
__device__ uint32_t g_w3m[CC];
__device__ float    g_inv3[CC], g_bb3[CC];

// Scratch: h1 binarized activations, 32 channels packed per pixel. 1 MB.
__device__ uint32_t g_h1b[BB * HW];

// ---------------------------------------------------------------------------
// Prep: ONE mask word per warp (544 words over 68 blocks x 8 warps) ->
// exactly one load+ballot per warp, all DRAM latency overlapped.
// bit c = (w > 0);  bn(z) = z*inv + bb, inv = g/sqrt(v+eps) > 0, bb = b - m*inv
// ---------------------------------------------------------------------------
__global__ void __launch_bounds__(256) prep_kernel(
    const float* __restrict__ w1, const float* __restrict__ g1,
    const float* __restrict__ b1, const float* __restrict__ m1, const float* __restrict__ v1,
    const float* __restrict__ w2, const float* __restrict__ g2,
    const float* __restrict__ b2, const float* __restrict__ m2, const float* __restrict__ v2,
    const float* __restrict__ w3, const float* __restrict__ g3,
    const float* __restrict__ b3, const float* __restrict__ m3, const float* __restrict__ v3)
{
    int tid  = threadIdx.x;
    int lane = tid & 31;
    int gw   = blockIdx.x * 8 + (tid >> 5);   // global word id 0..543

    if (gw < 128) {
        int oc = gw >> 2, j = gw & 3;
        uint32_t m = __ballot_sync(0xffffffffu, w1[oc * CC + j * 32 + lane] > 0.f);
        if (lane == 0) g_w1m[oc][j] = m;
    } else if (gw < 416) {
        int idx = gw - 128;
        int oc = idx / 9, t9 = idx - oc * 9;
        uint32_t m = __ballot_sync(0xffffffffu, w2[oc * (CI * 9) + lane * 9 + t9] > 0.f);
        if (lane == 0) g_w2m[oc][t9] = m;
    } else if (gw < 544) {
        int c = gw - 416;
        uint32_t m = __ballot_sync(0xffffffffu, w3[c * CI + lane] > 0.f);
        if (lane == 0) g_w3m[c] = m;
    }

    if (blockIdx.x == 0) {
        if (tid < CI) {
            float inv = __fdiv_rn(g1[tid], __fsqrt_rn(__fadd_rn(v1[tid], 1e-5f)));
            g_inv1[tid] = inv;
            g_bb1[tid]  = __fadd_rn(b1[tid], -__fmul_rn(m1[tid], inv));
        } else if (tid >= 64 && tid < 64 + CI) {
            int t = tid - 64;
            float inv = __fdiv_rn(g2[t], __fsqrt_rn(__fadd_rn(v2[t], 1e-5f)));
            g_inv2[t] = inv;
            g_bb2[t]  = __fadd_rn(b2[t], -__fmul_rn(m2[t], inv));
        } else if (tid >= 128) {
            int t = tid - 128;
            float inv = __fdiv_rn(g3[t], __fsqrt_rn(__fadd_rn(v3[t], 1e-5f)));
            g_inv3[t] = inv;
            g_bb3[t]  = __fadd_rn(b3[t], -__fmul_rn(m3[t], inv));
        }
    }
}

// ---------------------------------------------------------------------------
// Kernel A: conv1 (1x1, 128->32) + bn + sign -> packed h1 bitmask per pixel.
// 4 pixels/thread via float4; 128 threads/block; 512 blocks.
// ---------------------------------------------------------------------------
__global__ void __launch_bounds__(128) k_conv1(const float* __restrict__ x)
{
    __shared__ uint32_t sw1[CI][4];
    __shared__ float sinv1[CI], sbb1[CI];
    int tid = threadIdx.x;
    if (tid < CI) {
        sinv1[tid] = g_inv1[tid]; sbb1[tid] = g_bb1[tid];
        #pragma unroll
        for (int j = 0; j < 4; j++) sw1[tid][j] = g_w1m[tid][j];
    }
    __syncthreads();

    int t   = blockIdx.x * 128 + tid;        // 0..65535
    int px0 = t * 4;                          // 4 consecutive pixels, same batch
    int b   = px0 / HW;
    int p   = px0 - b * HW;
    const float4* xp = (const float4*)(x + (size_t)b * (CC * HW) + p);
    const int cs = HW / 4;                    // channel stride in float4s

    // Sign masks: s[j] bit i = sign of channel j*32+i, one set per pixel.
    uint32_t s0[4] = {0,0,0,0}, s1[4] = {0,0,0,0},
             s2[4] = {0,0,0,0}, s3[4] = {0,0,0,0};
    #pragma unroll
    for (int j = 0; j < 4; j++) {
        #pragma unroll 8
        for (int i = 0; i < 32; i++) {
            float4 v = xp[(j * 32 + i) * cs];
            if (v.x > 0.f) s0[j] |= (1u << i);
            if (v.y > 0.f) s1[j] |= (1u << i);
            if (v.z > 0.f) s2[j] |= (1u << i);
            if (v.w > 0.f) s3[j] |= (1u << i);
        }
    }

    uint32_t o0 = 0, o1 = 0, o2 = 0, o3 = 0;
    #pragma unroll
    for (int oc = 0; oc < CI; oc++) {
        uint32_t wa = sw1[oc][0], wb = sw1[oc][1], wc = sw1[oc][2], wd = sw1[oc][3];
        float inv = sinv1[oc], bb = sbb1[oc];
        int p0 = __popc(s0[0]^wa) + __popc(s0[1]^wb) + __popc(s0[2]^wc) + __popc(s0[3]^wd);
        int p1 = __popc(s1[0]^wa) + __popc(s1[1]^wb) + __popc(s1[2]^wc) + __popc(s1[3]^wd);
        int p2 = __popc(s2[0]^wa) + __popc(s2[1]^wb) + __popc(s2[2]^wc) + __popc(s2[3]^wd);
        int p3 = __popc(s3[0]^wa) + __popc(s3[1]^wb) + __popc(s3[2]^wc) + __popc(s3[3]^wd);
        if (__fadd_rn(__fmul_rn((float)(128 - 2*p0), inv), bb) > 0.f) o0 |= (1u << oc);
        if (__fadd_rn(__fmul_rn((float)(128 - 2*p1), inv), bb) > 0.f) o1 |= (1u << oc);
        if (__fadd_rn(__fmul_rn((float)(128 - 2*p2), inv), bb) > 0.f) o2 |= (1u << oc);
        if (__fadd_rn(__fmul_rn((float)(128 - 2*p3), inv), bb) > 0.f) o3 |= (1u << oc);
    }
    ((uint4*)g_h1b)[t] = make_uint4(o0, o1, o2, o3);
}

// ---------------------------------------------------------------------------
// Kernel B: conv2 (3x3, zero-pad AFTER binarize) + conv3 (1x1, 32->128)
//           + bn + prelu + residual + prelu. 4 pixels/thread, float4 I/O.
// Neighbor masks read straight from g_h1b (1 MB, L2-resident) -- no smem tile.
// ---------------------------------------------------------------------------
__global__ void __launch_bounds__(128) k_main(
    const float* __restrict__ x, float* __restrict__ out,
    const float* __restrict__ a3p, const float* __restrict__ aoutp)
{
    __shared__ uint32_t sw2[CI][9];
    __shared__ float sinv2[CI], sbb2[CI];
    __shared__ uint32_t sw3[CC];
    __shared__ float sinv3[CC], sbb3[CC];

    int tid = threadIdx.x;
    if (tid < CC) { sw3[tid] = g_w3m[tid]; sinv3[tid] = g_inv3[tid]; sbb3[tid] = g_bb3[tid]; }
    if (tid < CI) {
        sinv2[tid] = g_inv2[tid]; sbb2[tid] = g_bb2[tid];
        #pragma unroll
        for (int t9 = 0; t9 < 9; t9++) sw2[tid][t9] = g_w2m[tid][t9];
    }
    __syncthreads();

    int t   = blockIdx.x * 128 + tid;        // 0..65535
    int px0 = t * 4;
    int b   = px0 / HW;
    int p   = px0 - b * HW;
    int h   = p / WW;
    int w   = p - h * WW;                     // multiple of 4, w+3 <= 255

    // Load the 3x6 neighbor-mask window (rows h-1..h+1, cols w-1..w+4).
    const uint32_t* hb = g_h1b + (size_t)b * HW;
    uint32_t nm[3][6];
    bool vy[3], vc[6];
    #pragma unroll
    for (int r = 0; r < 3; r++) { int y = h + r - 1; vy[r] = (y >= 0) & (y < HH); }
    #pragma unroll
    for (int c = 0; c < 6; c++) { int xx = w + c - 1; vc[c] = (xx >= 0) & (xx < WW); }
    #pragma unroll
    for (int r = 0; r < 3; r++) {
        int y = h + r - 1;
        #pragma unroll
        for (int c = 0; c < 6; c++) {
            int xx = w + c - 1;
            nm[r][c] = (vy[r] & vc[c]) ? __ldg(hb + y * WW + xx) : 0u;
        }
    }

    const bool interior = (h > 0) & (h < HH - 1) & (w > 0) & (w + 4 < WW);

    uint32_t h2[4] = {0,0,0,0};
    if (interior) {
        #pragma unroll
        for (int oc = 0; oc < CI; oc++) {
            float inv = sinv2[oc], bb = sbb2[oc];
            #pragma unroll
            for (int j = 0; j < 4; j++) {
                int pc = 0;
                #pragma unroll
                for (int r = 0; r < 3; r++)
                    #pragma unroll
                    for (int dc = 0; dc < 3; dc++)
                        pc += __popc(nm[r][j + dc] ^ sw2[oc][r * 3 + dc]);
                float v = __fadd_rn(__fmul_rn((float)(288 - 2 * pc), inv), bb);
                if (v > 0.f) h2[j] |= (1u << oc);
            }
        }
    } else {
        #pragma unroll
        for (int oc = 0; oc < CI; oc++) {
            float inv = sinv2[oc], bb = sbb2[oc];
            #pragma unroll
            for (int j = 0; j < 4; j++) {
                int z = 0;
                #pragma unroll
                for (int r = 0; r < 3; r++)
                    #pragma unroll
                    for (int dc = 0; dc < 3; dc++) {
                        int c9 = 32 - 2 * __popc(nm[r][j + dc] ^ sw2[oc][r * 3 + dc]);
                        z += (vy[r] & vc[j + dc]) ? c9 : 0;
                    }
                float v = __fadd_rn(__fmul_rn((float)z, inv), bb);
                if (v > 0.f) h2[j] |= (1u << oc);
            }
        }
    }

    // conv3 + bn + prelu + residual + prelu, float4 per channel.
    float a3   = a3p[0];
    float aout = aoutp[0];
    const float4* xp = (const float4*)(x + (size_t)b * (CC * HW) + p);
    float4* op       = (float4*)(out + (size_t)b * (CC * HW) + p);
    const int cs = HW / 4;

    #pragma unroll 8
    for (int c = 0; c < CC; c++) {
        uint32_t wc = sw3[c];
        float inv = sinv3[c], bb = sbb3[c];
        float v0 = __fadd_rn(__fmul_rn((float)(32 - 2 * __popc(h2[0] ^ wc)), inv), bb);
        float v1 = __fadd_rn(__fmul_rn((float)(32 - 2 * __popc(h2[1] ^ wc)), inv), bb);
        float v2 = __fadd_rn(__fmul_rn((float)(32 - 2 * __popc(h2[2] ^ wc)), inv), bb);
        float v3 = __fadd_rn(__fmul_rn((float)(32 - 2 * __popc(h2[3] ^ wc)), inv), bb);
        v0 = (v0 >= 0.f) ? v0 : a3 * v0;
        v1 = (v1 >= 0.f) ? v1 : a3 * v1;
        v2 = (v2 >= 0.f) ? v2 : a3 * v2;
        v3 = (v3 >= 0.f) ? v3 : a3 * v3;
        float4 xv = xp[c * cs];
        float s0 = v0 + xv.x, s1 = v1 + xv.y, s2 = v2 + xv.z, s3 = v3 + xv.w;
        s0 = (s0 >= 0.f) ? s0 : aout * s0;
        s1 = (s1 >= 0.f) ? s1 : aout * s1;
        s2 = (s2 >= 0.f) ? s2 : aout * s2;
        s3 = (s3 >= 0.f) ? s3 : aout * s3;
        __stwt(op + c * cs, make_float4(s0, s1, s2, s3));
    }
}

// ---------------------------------------------------------------------------
extern "C" void kernel_launch(void* const* d_in, const int* in_sizes, int n_in,
                              void* d_out, int out_size)
{
    const float* x  = (const float*)d_in[0];
    const float* w1 = (const float*)d_in[1];
    const float* g1 = (const float*)d_in[2];
    const float* b1 = (const float*)d_in[3];
    const float* m1 = (const float*)d_in[4];
    const float* v1 = (const float*)d_in[5];
    // d_in[6] = a1 (unused: prelu with a>0 never changes the following sign)
    const float* w2 = (const float*)d_in[7];
    const float* g2 = (const float*)d_in[8];
    const float* b2 = (const float*)d_in[9];
    const float* m2 = (const float*)d_in[10];
    const float* v2 = (const float*)d_in[11];
    // d_in[12] = a2 (unused, same reason)
    const float* w3 = (const float*)d_in[13];
    const float* g3 = (const float*)d_in[14];
    const float* b3 = (const float*)d_in[15];
    const float* m3 = (const float*)d_in[16];
    const float* v3 = (const float*)d_in[17];
    const float* a3 = (const float*)d_in[18];
    const float* ao = (const float*)d_in[19];
    float* out = (float*)d_out;

    prep_kernel<<<68, 256>>>(w1, g1, b1, m1, v1,
                             w2, g2, b2, m2, v2,
                             w3, g3, b3, m3, v3);

    // 65536 threads each: conv1 then conv2+3, 4 px/thread, 512 blocks each.
    k_conv1<<<512, 128>>>(x);
    k_main<<<512, 128>>>(x, out, a3, ao);
}

// round 9
// speedup vs baseline: 1.4896x; 1.4896x over previous
#include <cuda_runtime.h>
#include <stdint.h>

#define CC   128
#define CI   32
#define HH   128
#define WW   256
#define BB   8
#define HW   (HH*WW)

// Precomputed parameters (filled by prep kernel each launch; deterministic).
__device__ uint32_t g_w1m[CI][4];
__device__ float    g_inv1[CI], g_bb1[CI];
__device__ uint32_t g_w2m[CI][9];
__device__ float    g_inv2[CI], g_bb2[CI];
__device__ uint32_t g_w3m[CC];
__device__ float    g_inv3[CC], g_bb3[CC];

// Scratch: h1 binarized activations, 32 channels packed per pixel. 1 MB.
__device__ uint32_t g_h1b[BB * HW];

// ---------------------------------------------------------------------------
// Prep: ONE mask word per warp (544 words over 68 blocks x 8 warps) ->
// exactly one load+ballot per warp, all DRAM latency overlapped. (5.9us meas.)
// bit c = (w > 0);  bn(z) = z*inv + bb, inv = g/sqrt(v+eps) > 0, bb = b - m*inv
// ---------------------------------------------------------------------------
__global__ void __launch_bounds__(256) prep_kernel(
    const float* __restrict__ w1, const float* __restrict__ g1,
    const float* __restrict__ b1, const float* __restrict__ m1, const float* __restrict__ v1,
    const float* __restrict__ w2, const float* __restrict__ g2,
    const float* __restrict__ b2, const float* __restrict__ m2, const float* __restrict__ v2,
    const float* __restrict__ w3, const float* __restrict__ g3,
    const float* __restrict__ b3, const float* __restrict__ m3, const float* __restrict__ v3)
{
    int tid  = threadIdx.x;
    int lane = tid & 31;
    int gw   = blockIdx.x * 8 + (tid >> 5);   // global word id 0..543

    if (gw < 128) {
        int oc = gw >> 2, j = gw & 3;
        uint32_t m = __ballot_sync(0xffffffffu, w1[oc * CC + j * 32 + lane] > 0.f);
        if (lane == 0) g_w1m[oc][j] = m;
    } else if (gw < 416) {
        int idx = gw - 128;
        int oc = idx / 9, t9 = idx - oc * 9;
        uint32_t m = __ballot_sync(0xffffffffu, w2[oc * (CI * 9) + lane * 9 + t9] > 0.f);
        if (lane == 0) g_w2m[oc][t9] = m;
    } else if (gw < 544) {
        int c = gw - 416;
        uint32_t m = __ballot_sync(0xffffffffu, w3[c * CI + lane] > 0.f);
        if (lane == 0) g_w3m[c] = m;
    }

    if (blockIdx.x == 0) {
        if (tid < CI) {
            float inv = __fdiv_rn(g1[tid], __fsqrt_rn(__fadd_rn(v1[tid], 1e-5f)));
            g_inv1[tid] = inv;
            g_bb1[tid]  = __fadd_rn(b1[tid], -__fmul_rn(m1[tid], inv));
        } else if (tid >= 64 && tid < 64 + CI) {
            int t = tid - 64;
            float inv = __fdiv_rn(g2[t], __fsqrt_rn(__fadd_rn(v2[t], 1e-5f)));
            g_inv2[t] = inv;
            g_bb2[t]  = __fadd_rn(b2[t], -__fmul_rn(m2[t], inv));
        } else if (tid >= 128) {
            int t = tid - 128;
            float inv = __fdiv_rn(g3[t], __fsqrt_rn(__fadd_rn(v3[t], 1e-5f)));
            g_inv3[t] = inv;
            g_bb3[t]  = __fadd_rn(b3[t], -__fmul_rn(m3[t], inv));
        }
    }
}

// ---------------------------------------------------------------------------
// Kernel A: conv1 (1x1, 128->32) + bn + sign -> packed h1 bitmask per pixel.
// 1 px/thread, 256 threads, 1024 blocks (R6 config, proven fastest).
// ---------------------------------------------------------------------------
__global__ void __launch_bounds__(256) k_conv1(const float* __restrict__ x)
{
    __shared__ uint32_t sw1[CI][4];
    __shared__ float sinv1[CI], sbb1[CI];
    int tid = threadIdx.x;
    if (tid < CI) {
        sinv1[tid] = g_inv1[tid]; sbb1[tid] = g_bb1[tid];
        #pragma unroll
        for (int j = 0; j < 4; j++) sw1[tid][j] = g_w1m[tid][j];
    }
    __syncthreads();

    int px = blockIdx.x * 256 + tid;     // 0 .. B*H*W-1 (exact multiple)
    int b  = px / HW;
    int p  = px - b * HW;
    const float* xp = x + (size_t)b * (CC * HW) + p;

    uint32_t s0 = 0, s1 = 0, s2 = 0, s3 = 0;
    #pragma unroll
    for (int i = 0; i < 32; i++) {
        if (xp[(i      ) * HW] > 0.f) s0 |= (1u << i);
        if (xp[(i +  32) * HW] > 0.f) s1 |= (1u << i);
        if (xp[(i +  64) * HW] > 0.f) s2 |= (1u << i);
        if (xp[(i +  96) * HW] > 0.f) s3 |= (1u << i);
    }

    uint32_t outm = 0;
    #pragma unroll
    for (int oc = 0; oc < CI; oc++) {
        int pc = __popc(s0 ^ sw1[oc][0]) + __popc(s1 ^ sw1[oc][1])
               + __popc(s2 ^ sw1[oc][2]) + __popc(s3 ^ sw1[oc][3]);
        float z = (float)(128 - 2 * pc);
        float v = __fadd_rn(__fmul_rn(z, sinv1[oc]), sbb1[oc]);
        if (v > 0.f) outm |= (1u << oc);
    }
    g_h1b[px] = outm;
}

// ---------------------------------------------------------------------------
// Kernel B: conv2 (3x3, zero-pad AFTER binarize) + conv3 (1x1, 32->128)
//           + bn + prelu + residual + prelu. Tile 32(W) x 8(H), 1 px/thread.
// ---------------------------------------------------------------------------
#define TW 32
#define TH 8

__global__ void __launch_bounds__(256) k_main(
    const float* __restrict__ x, float* __restrict__ out,
    const float* __restrict__ a3p, const float* __restrict__ aoutp)
{
    __shared__ uint32_t sh1[TH + 2][TW + 2];
    __shared__ uint32_t sw2[CI][9];
    __shared__ float sinv2[CI], sbb2[CI];
    __shared__ uint32_t sw3[CC];
    __shared__ float sinv3[CC], sbb3[CC];

    int tid = threadIdx.x;
    int tx = tid & (TW - 1);
    int ty = tid / TW;
    int w0 = blockIdx.x * TW;
    int h0 = blockIdx.y * TH;
    int b  = blockIdx.z;

    if (tid < CC) { sw3[tid] = g_w3m[tid]; sinv3[tid] = g_inv3[tid]; sbb3[tid] = g_bb3[tid]; }
    if (tid < CI) {
        sinv2[tid] = g_inv2[tid]; sbb2[tid] = g_bb2[tid];
        #pragma unroll
        for (int t9 = 0; t9 < 9; t9++) sw2[tid][t9] = g_w2m[tid][t9];
    }

    const bool border = (w0 == 0) | (h0 == 0) | (w0 + TW == WW) | (h0 + TH == HH);

    // Load h1 bitmask tile + 1-pixel halo
    const uint32_t* h1b = g_h1b + (size_t)b * HW;
    for (int it = tid; it < (TH + 2) * (TW + 2); it += 256) {
        int hy = it / (TW + 2), hx = it - hy * (TW + 2);
        int gh = h0 + hy - 1, gw = w0 + hx - 1;
        uint32_t v = 0;
        if (gh >= 0 && gh < HH && gw >= 0 && gw < WW) v = h1b[gh * WW + gw];
        sh1[hy][hx] = v;
    }
    __syncthreads();

    int gh = h0 + ty, gw = w0 + tx;

    // conv2 neighborhood masks: center at sh1[ty+1][tx+1]; tap t offset
    // (t/3-1, t%3-1) -> gather sh1[ty + t/3][tx + t%3].
    uint32_t n[9];
    #pragma unroll
    for (int t = 0; t < 9; t++)
        n[t] = sh1[ty + t / 3][tx + t % 3];

    uint32_t h2b = 0;
    if (!border) {
        // Interior: all 9 taps valid -> z = 288 - 2 * sum(popc)
        #pragma unroll
        for (int oc = 0; oc < CI; oc++) {
            int pc = 0;
            #pragma unroll
            for (int t = 0; t < 9; t++) pc += __popc(n[t] ^ sw2[oc][t]);
            float v = __fadd_rn(__fmul_rn((float)(288 - 2 * pc), sinv2[oc]), sbb2[oc]);
            if (v > 0.f) h2b |= (1u << oc);
        }
    } else {
        bool ok[9];
        #pragma unroll
        for (int t = 0; t < 9; t++) {
            int yy = gh + t / 3 - 1, xx = gw + t % 3 - 1;
            ok[t] = (yy >= 0) & (yy < HH) & (xx >= 0) & (xx < WW);
        }
        #pragma unroll
        for (int oc = 0; oc < CI; oc++) {
            int z = 0;
            #pragma unroll
            for (int t = 0; t < 9; t++) {
                int c9 = 32 - 2 * __popc(n[t] ^ sw2[oc][t]);
                z += ok[t] ? c9 : 0;
            }
            float v = __fadd_rn(__fmul_rn((float)z, sinv2[oc]), sbb2[oc]);
            if (v > 0.f) h2b |= (1u << oc);
        }
    }

    // conv3 + bn + prelu + residual + prelu
    float a3   = a3p[0];
    float aout = aoutp[0];
    size_t base = (size_t)b * (CC * HW) + (size_t)gh * WW + gw;
    const float* xp = x + base;
    float* op = out + base;

    #pragma unroll 16
    for (int c = 0; c < CC; c++) {
        int z = 32 - 2 * __popc(h2b ^ sw3[c]);
        float v = __fadd_rn(__fmul_rn((float)z, sinv3[c]), sbb3[c]);
        v = (v >= 0.f) ? v : a3 * v;
        float s = v + xp[(size_t)c * HW];
        s = (s >= 0.f) ? s : aout * s;
        __stwt(op + (size_t)c * HW, s);
    }
}

// ---------------------------------------------------------------------------
extern "C" void kernel_launch(void* const* d_in, const int* in_sizes, int n_in,
                              void* d_out, int out_size)
{
    const float* x  = (const float*)d_in[0];
    const float* w1 = (const float*)d_in[1];
    const float* g1 = (const float*)d_in[2];
    const float* b1 = (const float*)d_in[3];
    const float* m1 = (const float*)d_in[4];
    const float* v1 = (const float*)d_in[5];
    // d_in[6] = a1 (unused: prelu with a>0 never changes the following sign)
    const float* w2 = (const float*)d_in[7];
    const float* g2 = (const float*)d_in[8];
    const float* b2 = (const float*)d_in[9];
    const float* m2 = (const float*)d_in[10];
    const float* v2 = (const float*)d_in[11];
    // d_in[12] = a2 (unused, same reason)
    const float* w3 = (const float*)d_in[13];
    const float* g3 = (const float*)d_in[14];
    const float* b3 = (const float*)d_in[15];
    const float* m3 = (const float*)d_in[16];
    const float* v3 = (const float*)d_in[17];
    const float* a3 = (const float*)d_in[18];
    const float* ao = (const float*)d_in[19];
    float* out = (float*)d_out;

    prep_kernel<<<68, 256>>>(w1, g1, b1, m1, v1,
                             w2, g2, b2, m2, v2,
                             w3, g3, b3, m3, v3);

    // R6 config verbatim: full grids, scalar access, high thread count.
    k_conv1<<<(BB * HW) / 256, 256>>>(x);

    dim3 grid(WW / TW, HH / TH, BB);   // 8 x 16 x 8 = 1024 blocks
    k_main<<<grid, 256>>>(x, out, a3, ao);
}